// round 7
// baseline (speedup 1.0000x reference)
#include <cuda_runtime.h>
#include <cuda_bf16.h>

// Problem constants (fixed by the reference setup)
constexpr int B        = 16;
constexpr int H        = 16;
constexpr int D        = 128;
constexpr int BS       = 16;    // tokens per physical KV block
constexpr int BPS      = 128;   // blocks per sequence
constexpr int NSPLIT   = 16;
constexpr int CHUNK    = 128;   // tokens per split (NSPLIT*CHUNK = 2048)
constexpr int NW       = 8;     // warps per CTA
constexpr int THREADS  = NW * 32;
constexpr int TPW      = 4;     // tokens per warp per iteration

// Scratch for split-KV partials (no cudaMalloc allowed)
__device__ float g_part_acc[B * H * NSPLIT * D];   // 2 MB
__device__ float2 g_part_ml[B * H * NSPLIT];       // (m, l) per partial

__device__ __forceinline__ float warp_sum(float v) {
    v += __shfl_xor_sync(0xffffffffu, v, 16);
    v += __shfl_xor_sync(0xffffffffu, v, 8);
    v += __shfl_xor_sync(0xffffffffu, v, 4);
    v += __shfl_xor_sync(0xffffffffu, v, 2);
    v += __shfl_xor_sync(0xffffffffu, v, 1);
    return v;
}
__device__ __forceinline__ float warp_max(float v) {
    v = fmaxf(v, __shfl_xor_sync(0xffffffffu, v, 16));
    v = fmaxf(v, __shfl_xor_sync(0xffffffffu, v, 8));
    v = fmaxf(v, __shfl_xor_sync(0xffffffffu, v, 4));
    v = fmaxf(v, __shfl_xor_sync(0xffffffffu, v, 2));
    v = fmaxf(v, __shfl_xor_sync(0xffffffffu, v, 1));
    return v;
}

// ---------------------------------------------------------------------------
// Kernel 1: per-(b,h,split) partial attention, two-pass, MLP=4 per warp.
// Finer granularity (128-token chunks, 4096 CTAs) for wave balance.
// Inactive splits exit immediately WITHOUT writing (combine is ctx-aware).
// K/V loads unguarded (block_tables fully populated); scores masked only.
// ---------------------------------------------------------------------------
__global__ __launch_bounds__(THREADS)
void pa_split_kernel(const float* __restrict__ q,
                     const float* __restrict__ kc,
                     const float* __restrict__ vc,
                     const int*   __restrict__ bt,
                     const int*   __restrict__ cl)
{
    __shared__ float  sc[CHUNK + TPW];        // padded score buffer
    __shared__ float4 wacc4[NW][D / 4];       // 4 KB
    __shared__ int    sblk[CHUNK / BS + 1];   // padded block ids
    __shared__ float  red[NW];
    __shared__ float  s_m;

    const int tid  = threadIdx.x;
    const int lane = tid & 31;
    const int wid  = tid >> 5;

    const int s  = blockIdx.x & (NSPLIT - 1);
    const int bh = blockIdx.x >> 4;          // b*H + h
    const int b  = bh >> 4;
    const int h  = bh & 15;

    const int ctx   = cl[b];
    const int t0    = s * CHUNK;
    const int pbase = bh * NSPLIT + s;

    int n = ctx - t0;
    if (n <= 0) return;                       // inactive: combine skips us
    if (n > CHUNK) n = CHUNK;

    // Block ids for this chunk, +1 pad entry (clamped to a valid table slot).
    if (tid < CHUNK / BS + 1) {
        int idx = s * (CHUNK / BS) + tid;
        if (idx > BPS - 1) idx = BPS - 1;
        sblk[tid] = bt[b * BPS + idx];
    }
    // Zero the pad region of the score buffer (pass-2 overrun reads p=0).
    if (tid < TPW) sc[CHUNK + tid] = 0.0f;

    const float4 q4 = reinterpret_cast<const float4*>(q + (size_t)bh * D)[lane];
    __syncthreads();

    const float scale = 0.08838834764831845f;   // 1/sqrt(128)

    // ---- Pass 1: scores, 4 tokens/warp/iter, unguarded loads ---------------
    for (int t = TPW * wid; t < n; t += TPW * NW) {
        float4 kk[TPW];
        #pragma unroll
        for (int j = 0; j < TPW; ++j) {
            const int tt = t + j;
            const size_t off = (((size_t)sblk[tt >> 4] * BS + (tt & 15)) * H + h) * D;
            kk[j] = reinterpret_cast<const float4*>(kc + off)[lane];
        }

        float d[TPW];
        #pragma unroll
        for (int j = 0; j < TPW; ++j)
            d[j] = kk[j].x * q4.x + kk[j].y * q4.y + kk[j].z * q4.z + kk[j].w * q4.w;

        #pragma unroll
        for (int mask = 16; mask; mask >>= 1) {
            #pragma unroll
            for (int j = 0; j < TPW; ++j)
                d[j] += __shfl_xor_sync(0xffffffffu, d[j], mask);
        }

        if (lane == 0) {
            #pragma unroll
            for (int j = 0; j < TPW; ++j)
                if (t + j < n) sc[t + j] = d[j] * scale;
        }
    }
    __syncthreads();

    // ---- Block softmax over the chunk ---------------------------------------
    float v = (tid < n) ? sc[tid] : -3.0e38f;
    float m = warp_max(v);
    if (lane == 0) red[wid] = m;
    __syncthreads();
    if (wid == 0) {
        float x = (lane < NW) ? red[lane] : -3.0e38f;
        x = warp_max(x);
        if (lane == 0) s_m = x;
    }
    __syncthreads();
    const float M = s_m;

    const float p = (tid < n) ? __expf(v - M) : 0.0f;
    if (tid < CHUNK) sc[tid] = p;     // invalid slots get 0 -> pass 2 unguarded
    float l = warp_sum(p);
    if (lane == 0) red[wid] = l;
    __syncthreads();

    // ---- Pass 2: weighted V accumulation, 4 tokens/warp/iter, unguarded -----
    float4 acc = make_float4(0.f, 0.f, 0.f, 0.f);
    for (int t = TPW * wid; t < n; t += TPW * NW) {
        float  pp[TPW];
        float4 vv[TPW];
        #pragma unroll
        for (int j = 0; j < TPW; ++j) pp[j] = sc[t + j];
        #pragma unroll
        for (int j = 0; j < TPW; ++j) {
            const int tt = t + j;
            const size_t off = (((size_t)sblk[tt >> 4] * BS + (tt & 15)) * H + h) * D;
            vv[j] = reinterpret_cast<const float4*>(vc + off)[lane];
        }
        #pragma unroll
        for (int j = 0; j < TPW; ++j) {
            acc.x += pp[j] * vv[j].x;
            acc.y += pp[j] * vv[j].y;
            acc.z += pp[j] * vv[j].z;
            acc.w += pp[j] * vv[j].w;
        }
    }
    wacc4[wid][lane] = acc;
    __syncthreads();

    if (tid < D) {
        const float* wf = reinterpret_cast<const float*>(wacc4);
        float o = 0.0f;
        #pragma unroll
        for (int w = 0; w < NW; ++w) o += wf[w * D + tid];
        g_part_acc[pbase * D + tid] = o;
    }
    if (tid == 0) {
        float L = 0.0f;
        #pragma unroll
        for (int w = 0; w < NW; ++w) L += red[w];
        g_part_ml[pbase] = make_float2(M, L);
    }
}

// ---------------------------------------------------------------------------
// Kernel 2: ctx-aware combine. Folds only the active splits; all loads are
// predicated + front-batched (independent) so latency is overlapped.
// ---------------------------------------------------------------------------
__global__ __launch_bounds__(D)
void pa_combine_kernel(const int* __restrict__ cl, float* __restrict__ out)
{
    const int bh = blockIdx.x;
    const int d  = threadIdx.x;
    const int b  = bh >> 4;

    int ctx = cl[b];
    if (ctx > NSPLIT * CHUNK) ctx = NSPLIT * CHUNK;
    const int n_act = (ctx + CHUNK - 1) / CHUNK;   // >= 1

    // Front-batched (m, l) loads: independent, predicated.
    float2 ml[NSPLIT];
    #pragma unroll
    for (int s = 0; s < NSPLIT; ++s)
        ml[s] = (s < n_act) ? g_part_ml[bh * NSPLIT + s]
                            : make_float2(-3.0e38f, 0.0f);

    float M = -3.0e38f;
    #pragma unroll
    for (int s = 0; s < NSPLIT; ++s) M = fmaxf(M, ml[s].x);

    // Front-batched acc loads: independent, predicated.
    float av[NSPLIT];
    #pragma unroll
    for (int s = 0; s < NSPLIT; ++s)
        av[s] = (s < n_act) ? g_part_acc[(bh * NSPLIT + s) * D + d] : 0.0f;

    float L = 0.0f, o = 0.0f;
    #pragma unroll
    for (int s = 0; s < NSPLIT; ++s) {
        const float f = __expf(ml[s].x - M);
        L += ml[s].y * f;
        o += av[s] * f;
    }
    out[bh * D + d] = o / L;
}

extern "C" void kernel_launch(void* const* d_in, const int* in_sizes, int n_in,
                              void* d_out, int out_size)
{
    const float* q  = (const float*)d_in[0];
    const float* kc = (const float*)d_in[1];
    const float* vc = (const float*)d_in[2];
    const int*   bt = (const int*)d_in[3];
    const int*   cl = (const int*)d_in[4];
    float* out = (float*)d_out;

    pa_split_kernel<<<B * H * NSPLIT, THREADS>>>(q, kc, vc, bt, cl);
    pa_combine_kernel<<<B * H, D>>>(cl, out);
}

// round 8
// speedup vs baseline: 1.0625x; 1.0625x over previous
#include <cuda_runtime.h>
#include <cuda_bf16.h>

// Problem constants (fixed by the reference setup)
constexpr int B        = 16;
constexpr int H        = 16;
constexpr int D        = 128;
constexpr int BS       = 16;    // tokens per physical KV block
constexpr int BPS      = 128;   // blocks per sequence
constexpr int NSPLIT   = 8;
constexpr int CHUNK    = 256;   // tokens per split (NSPLIT*CHUNK = 2048)
constexpr int NW       = 8;     // warps per CTA
constexpr int THREADS  = NW * 32;
constexpr int TPW      = 4;     // tokens per warp per iteration
constexpr int NITEMS   = B * H * NSPLIT;   // 2048 work items
constexpr int NCTA     = 148 * 8;          // one resident wave (8 CTAs/SM)

// Scratch for split-KV partials (no cudaMalloc allowed)
__device__ float  g_part_acc[B * H * NSPLIT * D];   // 1 MB
__device__ float2 g_part_ml [B * H * NSPLIT];       // (m, l) per partial
__device__ unsigned int g_ticket;                   // work-queue counter (reset by combine)

__device__ __forceinline__ float warp_sum(float v) {
    v += __shfl_xor_sync(0xffffffffu, v, 16);
    v += __shfl_xor_sync(0xffffffffu, v, 8);
    v += __shfl_xor_sync(0xffffffffu, v, 4);
    v += __shfl_xor_sync(0xffffffffu, v, 2);
    v += __shfl_xor_sync(0xffffffffu, v, 1);
    return v;
}
__device__ __forceinline__ float warp_max(float v) {
    v = fmaxf(v, __shfl_xor_sync(0xffffffffu, v, 16));
    v = fmaxf(v, __shfl_xor_sync(0xffffffffu, v, 8));
    v = fmaxf(v, __shfl_xor_sync(0xffffffffu, v, 4));
    v = fmaxf(v, __shfl_xor_sync(0xffffffffu, v, 2));
    v = fmaxf(v, __shfl_xor_sync(0xffffffffu, v, 1));
    return v;
}

// ---------------------------------------------------------------------------
// Kernel 1: persistent CTAs + dynamic work queue over (b,h,split) items.
// Per item: two-pass partial attention (MLP=4/warp, unguarded K/V loads,
// scores masked). Inactive items (split beyond ctx) cost one fetch only.
// ---------------------------------------------------------------------------
__global__ __launch_bounds__(THREADS)
void pa_split_kernel(const float* __restrict__ q,
                     const float* __restrict__ kc,
                     const float* __restrict__ vc,
                     const int*   __restrict__ bt,
                     const int*   __restrict__ cl)
{
    __shared__ float  sc[CHUNK + TPW];        // padded score buffer
    __shared__ float4 wacc4[NW][D / 4];       // 4 KB
    __shared__ int    sblk[CHUNK / BS + 1];   // padded block ids
    __shared__ float  red[NW];
    __shared__ float  s_m;
    __shared__ unsigned int s_item;

    const int tid  = threadIdx.x;
    const int lane = tid & 31;
    const int wid  = tid >> 5;

    const float scale = 0.08838834764831845f;   // 1/sqrt(128)

    for (;;) {
        if (tid == 0) s_item = atomicAdd(&g_ticket, 1u);
        __syncthreads();
        const unsigned int item = s_item;
        __syncthreads();               // s_item consumed before next overwrite
        if (item >= (unsigned)NITEMS) return;

        const int s  = item & (NSPLIT - 1);
        const int bh = item >> 3;             // b*H + h
        const int b  = bh >> 4;
        const int h  = bh & 15;

        const int ctx   = cl[b];
        const int t0    = s * CHUNK;
        const int pbase = bh * NSPLIT + s;

        int n = ctx - t0;
        if (n <= 0) continue;                 // inactive: combine skips us
        if (n > CHUNK) n = CHUNK;

        // Block ids for this chunk, +1 pad (clamped to a valid table slot).
        if (tid < CHUNK / BS + 1) {
            int idx = s * (CHUNK / BS) + tid;
            if (idx > BPS - 1) idx = BPS - 1;
            sblk[tid] = bt[b * BPS + idx];
        }
        if (tid < TPW) sc[CHUNK + tid] = 0.0f;   // pad (pass-2 overrun -> p=0)

        const float4 q4 = reinterpret_cast<const float4*>(q + (size_t)bh * D)[lane];
        __syncthreads();

        // ---- Pass 1: scores, 4 tokens/warp/iter, unguarded loads -----------
        for (int t = TPW * wid; t < n; t += TPW * NW) {
            float4 kk[TPW];
            #pragma unroll
            for (int j = 0; j < TPW; ++j) {
                const int tt = t + j;
                const size_t off = (((size_t)sblk[tt >> 4] * BS + (tt & 15)) * H + h) * D;
                kk[j] = reinterpret_cast<const float4*>(kc + off)[lane];
            }

            float d[TPW];
            #pragma unroll
            for (int j = 0; j < TPW; ++j)
                d[j] = kk[j].x * q4.x + kk[j].y * q4.y + kk[j].z * q4.z + kk[j].w * q4.w;

            #pragma unroll
            for (int mask = 16; mask; mask >>= 1) {
                #pragma unroll
                for (int j = 0; j < TPW; ++j)
                    d[j] += __shfl_xor_sync(0xffffffffu, d[j], mask);
            }

            if (lane == 0) {
                #pragma unroll
                for (int j = 0; j < TPW; ++j)
                    if (t + j < n) sc[t + j] = d[j] * scale;
            }
        }
        __syncthreads();

        // ---- Block softmax over the chunk -----------------------------------
        float v = (tid < n) ? sc[tid] : -3.0e38f;
        float m = warp_max(v);
        if (lane == 0) red[wid] = m;
        __syncthreads();
        if (wid == 0) {
            float x = (lane < NW) ? red[lane] : -3.0e38f;
            x = warp_max(x);
            if (lane == 0) s_m = x;
        }
        __syncthreads();
        const float M = s_m;

        const float p = (tid < n) ? __expf(v - M) : 0.0f;
        sc[tid] = p;                  // invalid slots get 0 -> pass 2 unguarded
        float l = warp_sum(p);
        if (lane == 0) red[wid] = l;
        __syncthreads();

        // ---- Pass 2: weighted V accumulation, unguarded ----------------------
        float4 acc = make_float4(0.f, 0.f, 0.f, 0.f);
        for (int t = TPW * wid; t < n; t += TPW * NW) {
            float  pp[TPW];
            float4 vv[TPW];
            #pragma unroll
            for (int j = 0; j < TPW; ++j) pp[j] = sc[t + j];
            #pragma unroll
            for (int j = 0; j < TPW; ++j) {
                const int tt = t + j;
                const size_t off = (((size_t)sblk[tt >> 4] * BS + (tt & 15)) * H + h) * D;
                vv[j] = reinterpret_cast<const float4*>(vc + off)[lane];
            }
            #pragma unroll
            for (int j = 0; j < TPW; ++j) {
                acc.x += pp[j] * vv[j].x;
                acc.y += pp[j] * vv[j].y;
                acc.z += pp[j] * vv[j].z;
                acc.w += pp[j] * vv[j].w;
            }
        }
        wacc4[wid][lane] = acc;
        __syncthreads();

        if (tid < D) {
            const float* wf = reinterpret_cast<const float*>(wacc4);
            float o = 0.0f;
            #pragma unroll
            for (int w = 0; w < NW; ++w) o += wf[w * D + tid];
            g_part_acc[pbase * D + tid] = o;
        }
        if (tid == 0) {
            float L = 0.0f;
            #pragma unroll
            for (int w = 0; w < NW; ++w) L += red[w];
            g_part_ml[pbase] = make_float2(M, L);
        }
        __syncthreads();   // smem safe to reuse for next item
    }
}

// ---------------------------------------------------------------------------
// Kernel 2: ctx-aware combine (predicated, front-batched loads).
// Also resets the work-queue ticket for the next graph replay.
// ---------------------------------------------------------------------------
__global__ __launch_bounds__(D)
void pa_combine_kernel(const int* __restrict__ cl, float* __restrict__ out)
{
    if (blockIdx.x == 0 && threadIdx.x == 0) g_ticket = 0u;   // rearm queue

    const int bh = blockIdx.x;
    const int d  = threadIdx.x;
    const int b  = bh >> 4;

    int ctx = cl[b];
    if (ctx > NSPLIT * CHUNK) ctx = NSPLIT * CHUNK;
    const int n_act = (ctx + CHUNK - 1) / CHUNK;   // >= 1

    float2 ml[NSPLIT];
    #pragma unroll
    for (int s = 0; s < NSPLIT; ++s)
        ml[s] = (s < n_act) ? g_part_ml[bh * NSPLIT + s]
                            : make_float2(-3.0e38f, 0.0f);

    float M = -3.0e38f;
    #pragma unroll
    for (int s = 0; s < NSPLIT; ++s) M = fmaxf(M, ml[s].x);

    float av[NSPLIT];
    #pragma unroll
    for (int s = 0; s < NSPLIT; ++s)
        av[s] = (s < n_act) ? g_part_acc[(bh * NSPLIT + s) * D + d] : 0.0f;

    float L = 0.0f, o = 0.0f;
    #pragma unroll
    for (int s = 0; s < NSPLIT; ++s) {
        const float f = __expf(ml[s].x - M);
        L += ml[s].y * f;
        o += av[s] * f;
    }
    out[bh * D + d] = o / L;
}

extern "C" void kernel_launch(void* const* d_in, const int* in_sizes, int n_in,
                              void* d_out, int out_size)
{
    const float* q  = (const float*)d_in[0];
    const float* kc = (const float*)d_in[1];
    const float* vc = (const float*)d_in[2];
    const int*   bt = (const int*)d_in[3];
    const int*   cl = (const int*)d_in[4];
    float* out = (float*)d_out;

    pa_split_kernel<<<NCTA, THREADS>>>(q, kc, vc, bt, cl);
    pa_combine_kernel<<<B * H, D>>>(cl, out);
}

// round 9
// speedup vs baseline: 1.1096x; 1.0442x over previous
#include <cuda_runtime.h>
#include <cuda_bf16.h>

// Problem constants (fixed by the reference setup)
constexpr int B        = 16;
constexpr int H        = 16;
constexpr int D        = 128;
constexpr int BS       = 16;    // tokens per physical KV block
constexpr int BPS      = 128;   // blocks per sequence
constexpr int NSPLIT   = 16;
constexpr int CHUNK    = 128;   // tokens per split (NSPLIT*CHUNK = 2048)
constexpr int HG       = 4;     // heads per CTA (2KB-contiguous K/V reads)
constexpr int NHG      = H / HG;
constexpr int NW       = 8;     // warps per CTA
constexpr int THREADS  = NW * 32;

// Scratch for split-KV partials (no cudaMalloc allowed)
__device__ float  g_part_acc[B * H * NSPLIT * D];   // 2 MB
__device__ float2 g_part_ml [B * H * NSPLIT];       // (m, l) per partial

__device__ __forceinline__ float warp_sum(float v) {
    v += __shfl_xor_sync(0xffffffffu, v, 16);
    v += __shfl_xor_sync(0xffffffffu, v, 8);
    v += __shfl_xor_sync(0xffffffffu, v, 4);
    v += __shfl_xor_sync(0xffffffffu, v, 2);
    v += __shfl_xor_sync(0xffffffffu, v, 1);
    return v;
}
__device__ __forceinline__ float warp_max(float v) {
    v = fmaxf(v, __shfl_xor_sync(0xffffffffu, v, 16));
    v = fmaxf(v, __shfl_xor_sync(0xffffffffu, v, 8));
    v = fmaxf(v, __shfl_xor_sync(0xffffffffu, v, 4));
    v = fmaxf(v, __shfl_xor_sync(0xffffffffu, v, 2));
    v = fmaxf(v, __shfl_xor_sync(0xffffffffu, v, 1));
    return v;
}

// ---------------------------------------------------------------------------
// Kernel 1: CTA = (batch, head-group of 4, 128-token split).
// Warp per token: K/V loads are 4 consecutive LDG.128 spanning a CONTIGUOUS
// 2KB of the cache row (heads hg*4..hg*4+3 of one token) -> sequential DRAM
// bursts instead of scattered 512B granules. Two-pass block softmax per head.
// ---------------------------------------------------------------------------
__global__ __launch_bounds__(THREADS)
void pa_split_kernel(const float* __restrict__ q,
                     const float* __restrict__ kc,
                     const float* __restrict__ vc,
                     const int*   __restrict__ bt,
                     const int*   __restrict__ cl)
{
    __shared__ float  sc[HG][CHUNK];            // scores -> probabilities
    __shared__ float4 wacc4[NW][HG][32];        // 16 KB merge buffer
    __shared__ int    sblk[CHUNK / BS];
    __shared__ float  redm[HG][2], redl[HG][2];

    const int tid  = threadIdx.x;
    const int lane = tid & 31;
    const int wid  = tid >> 5;

    const int s  = blockIdx.x & (NSPLIT - 1);
    const int hg = (blockIdx.x >> 4) & (NHG - 1);
    const int b  = blockIdx.x >> 6;

    const int ctx = cl[b];
    const int t0  = s * CHUNK;

    int n = ctx - t0;
    if (n <= 0) return;                         // inactive: combine skips us
    if (n > CHUNK) n = CHUNK;

    if (tid < CHUNK / BS)
        sblk[tid] = bt[b * BPS + s * (CHUNK / BS) + tid];

    // Q for the 4 heads of this group (each lane holds its D-slice).
    const int h0 = hg * HG;
    float4 q4[HG];
    #pragma unroll
    for (int j = 0; j < HG; ++j)
        q4[j] = reinterpret_cast<const float4*>(q + ((size_t)b * H + h0 + j) * D)[lane];
    __syncthreads();

    const float scale = 0.08838834764831845f;   // 1/sqrt(128)

    // ---- Pass 1: scores. Warp per token; 4 heads = 2KB contiguous ---------
    for (int t = wid; t < n; t += NW) {
        const float* kt = kc + (((size_t)sblk[t >> 4] * BS + (t & 15)) * H + h0) * D;

        float4 kk[HG];
        #pragma unroll
        for (int j = 0; j < HG; ++j)
            kk[j] = reinterpret_cast<const float4*>(kt + j * D)[lane];

        float d[HG];
        #pragma unroll
        for (int j = 0; j < HG; ++j)
            d[j] = kk[j].x * q4[j].x + kk[j].y * q4[j].y +
                   kk[j].z * q4[j].z + kk[j].w * q4[j].w;

        #pragma unroll
        for (int mask = 16; mask; mask >>= 1) {
            #pragma unroll
            for (int j = 0; j < HG; ++j)
                d[j] += __shfl_xor_sync(0xffffffffu, d[j], mask);
        }

        if (lane == 0) {
            #pragma unroll
            for (int j = 0; j < HG; ++j)
                sc[j][t] = d[j] * scale;
        }
    }
    __syncthreads();

    // ---- Block softmax per head (2 warps per head, 64 tokens each) --------
    {
        const int h    = wid & (HG - 1);
        const int half = wid >> 2;               // 0 or 1
        const int t1   = half * 64 + lane;
        const int t2   = t1 + 32;

        const float v1 = (t1 < n) ? sc[h][t1] : -3.0e38f;
        const float v2 = (t2 < n) ? sc[h][t2] : -3.0e38f;

        const float mw = warp_max(fmaxf(v1, v2));
        if (lane == 0) redm[h][half] = mw;
        __syncthreads();

        const float M  = fmaxf(redm[h][0], redm[h][1]);
        const float p1 = (t1 < n) ? __expf(v1 - M) : 0.0f;
        const float p2 = (t2 < n) ? __expf(v2 - M) : 0.0f;
        sc[h][t1] = p1;
        sc[h][t2] = p2;

        const float lw = warp_sum(p1 + p2);
        if (lane == 0) redl[h][half] = lw;
    }
    __syncthreads();

    // ---- Pass 2: weighted V. Warp per token; 4 heads = 2KB contiguous -----
    float4 acc[HG];
    #pragma unroll
    for (int j = 0; j < HG; ++j) acc[j] = make_float4(0.f, 0.f, 0.f, 0.f);

    for (int t = wid; t < n; t += NW) {
        const float* vt = vc + (((size_t)sblk[t >> 4] * BS + (t & 15)) * H + h0) * D;

        float  pp[HG];
        float4 vv[HG];
        #pragma unroll
        for (int j = 0; j < HG; ++j) pp[j] = sc[j][t];   // broadcast LDS
        #pragma unroll
        for (int j = 0; j < HG; ++j)
            vv[j] = reinterpret_cast<const float4*>(vt + j * D)[lane];

        #pragma unroll
        for (int j = 0; j < HG; ++j) {
            acc[j].x += pp[j] * vv[j].x;
            acc[j].y += pp[j] * vv[j].y;
            acc[j].z += pp[j] * vv[j].z;
            acc[j].w += pp[j] * vv[j].w;
        }
    }
    #pragma unroll
    for (int j = 0; j < HG; ++j) wacc4[wid][j][lane] = acc[j];
    __syncthreads();

    // ---- Merge 8 warp partials and write (m, l, acc) ------------------------
    // 512 output floats (4 heads x 128 dims); 256 threads handle 2 each.
    const float* wf = reinterpret_cast<const float*>(wacc4);
    #pragma unroll
    for (int r = 0; r < 2; ++r) {
        const int idx = tid + r * THREADS;       // [0, 512)
        const int j   = idx >> 7;                // head within group
        const int d   = idx & 127;
        float o = 0.0f;
        #pragma unroll
        for (int w = 0; w < NW; ++w)
            o += wf[(w * HG + j) * D + d];
        const int pbase = ((b * H + h0 + j) * NSPLIT + s);
        g_part_acc[pbase * D + d] = o;
    }
    if (tid < HG) {
        const float M = fmaxf(redm[tid][0], redm[tid][1]);
        const float L = redl[tid][0] + redl[tid][1];
        g_part_ml[(b * H + h0 + tid) * NSPLIT + s] = make_float2(M, L);
    }
}

// ---------------------------------------------------------------------------
// Kernel 2: ctx-aware combine (predicated, front-batched loads).
// ---------------------------------------------------------------------------
__global__ __launch_bounds__(D)
void pa_combine_kernel(const int* __restrict__ cl, float* __restrict__ out)
{
    const int bh = blockIdx.x;
    const int d  = threadIdx.x;
    const int b  = bh >> 4;

    int ctx = cl[b];
    if (ctx > NSPLIT * CHUNK) ctx = NSPLIT * CHUNK;
    const int n_act = (ctx + CHUNK - 1) / CHUNK;   // >= 1

    float2 ml[NSPLIT];
    #pragma unroll
    for (int s = 0; s < NSPLIT; ++s)
        ml[s] = (s < n_act) ? g_part_ml[bh * NSPLIT + s]
                            : make_float2(-3.0e38f, 0.0f);

    float M = -3.0e38f;
    #pragma unroll
    for (int s = 0; s < NSPLIT; ++s) M = fmaxf(M, ml[s].x);

    float av[NSPLIT];
    #pragma unroll
    for (int s = 0; s < NSPLIT; ++s)
        av[s] = (s < n_act) ? g_part_acc[(bh * NSPLIT + s) * D + d] : 0.0f;

    float L = 0.0f, o = 0.0f;
    #pragma unroll
    for (int s = 0; s < NSPLIT; ++s) {
        const float f = __expf(ml[s].x - M);
        L += ml[s].y * f;
        o += av[s] * f;
    }
    out[bh * D + d] = o / L;
}

extern "C" void kernel_launch(void* const* d_in, const int* in_sizes, int n_in,
                              void* d_out, int out_size)
{
    const float* q  = (const float*)d_in[0];
    const float* kc = (const float*)d_in[1];
    const float* vc = (const float*)d_in[2];
    const int*   bt = (const int*)d_in[3];
    const int*   cl = (const int*)d_in[4];
    float* out = (float*)d_out;

    pa_split_kernel<<<B * NHG * NSPLIT, THREADS>>>(q, kc, vc, bt, cl);
    pa_combine_kernel<<<B * H, D>>>(cl, out);
}